// round 8
// baseline (speedup 1.0000x reference)
#include <cuda_runtime.h>
#include <cuda_fp16.h>
#include <cstdint>
#include <cstddef>

// 2-layer LSTM, T=1024, B=16, I=H=1024.
// Persistent per-layer kernels; register weights; direct-L2 A loads ordered
// x-LDG -> poll -> h-LDG -> GEMMs; one syncthreads/step (double-buffered red);
// per-cell-warp release flags with targeted 64-flag polls.
#define T_   1024
#define B_   16
#define H_   1024
#define NCTA 128
#define NTHR 256
#define WFRAG_L (NCTA*128*4*32*2)     // u32 per layer = 4,194,304
#define XFRAG_T 8192                  // u32 per timestep A-frag (32 KB)
#define HFRAG_SZ XFRAG_T
#define RED_STRIDE 544                // 16 rows * 34 floats per warp
#define NWFLAG 512

__device__ __align__(16) uint32_t g_wfrag[2][WFRAG_L];
__device__ __align__(16) uint32_t g_xfrag0[(size_t)T_*XFRAG_T];
__device__ __align__(16) uint32_t g_xfrag1[(size_t)T_*XFRAG_T];
__device__ __align__(16) uint32_t g_hfrag[2*HFRAG_SZ];
__device__ __align__(16) unsigned g_wflags[NWFLAG];

// ---------------------------------------------------------------------------
__global__ void k_reset() {
    int i = blockIdx.x * blockDim.x + threadIdx.x;
    if (i < 2*HFRAG_SZ) g_hfrag[i] = 0u;
    if (i < NWFLAG) g_wflags[i] = 0u;
}

// B-frag layout for [Wih;Whh]: idx = (((c*128+kk)*4+nt)*32+lane)*2+p
// lane=4g+tq ; W row = nt*H + c*8 + g ; k = (kk&63)*16 + 2tq + 8p + {0,1}
// kk<64 -> Wih, kk>=64 -> Whh
__global__ void k_conv_w(const float* __restrict__ Wih0, const float* __restrict__ Whh0,
                         const float* __restrict__ Wih1, const float* __restrict__ Whh1) {
    int layer = blockIdx.y;
    const float* Wih = layer ? Wih1 : Wih0;
    const float* Whh = layer ? Whh1 : Whh0;
    int stride = gridDim.x * blockDim.x;
    for (int idx = blockIdx.x * blockDim.x + threadIdx.x; idx < WFRAG_L; idx += stride) {
        int p    = idx & 1;
        int lane = (idx >> 1) & 31;
        int nt   = (idx >> 6) & 3;
        int kk   = (idx >> 8) & 127;
        int c    = idx >> 15;
        int g = lane >> 2, tq = lane & 3;
        int row = nt * H_ + c * 8 + g;
        int kl  = (kk & 63) * 16 + tq * 2 + p * 8;
        const float2 v = *reinterpret_cast<const float2*>(
            (kk < 64 ? Wih : Whh) + (size_t)row * H_ + kl);
        __half2 hv = __floats2half2_rn(v.x, v.y);
        g_wfrag[layer][idx] = *reinterpret_cast<uint32_t*>(&hv);
    }
}

// A-frag layout for x: per-t idx = (kk*32+lane)*4 + r ; b = g + 8*(r&1) ;
// k = kk*16 + 2tq + 8*(r>>1) + {0,1}
__global__ void k_conv_x(const float* __restrict__ x) {
    size_t total = (size_t)T_ * XFRAG_T;
    size_t stride = (size_t)gridDim.x * blockDim.x;
    for (size_t idx = (size_t)blockIdx.x * blockDim.x + threadIdx.x; idx < total; idx += stride) {
        int it = (int)(idx >> 13);
        int r8 = (int)(idx & (XFRAG_T - 1));
        int kk   = r8 >> 7;
        int lane = (r8 >> 2) & 31;
        int r    = r8 & 3;
        int g = lane >> 2, tq = lane & 3;
        int b  = g + ((r & 1) << 3);
        int kb = kk * 16 + tq * 2 + ((r >> 1) << 3);
        const float2 v = *reinterpret_cast<const float2*>(
            x + ((size_t)it * B_ + b) * H_ + kb);
        __half2 hv = __floats2half2_rn(v.x, v.y);
        g_xfrag0[idx] = *reinterpret_cast<uint32_t*>(&hv);
    }
}

// ---------------------------------------------------------------------------
__device__ __forceinline__ float tanh_ap(float v) {
    float r;
    asm("tanh.approx.f32 %0, %1;" : "=f"(r) : "f"(v));
    return r;
}
__device__ __forceinline__ float sigmoid_ap(float v) {
    return fmaf(tanh_ap(0.5f * v), 0.5f, 0.5f);
}

__device__ __forceinline__ uint4 ldcg4(const uint4* p) {
    uint4 v;
    asm volatile("ld.global.cg.v4.u32 {%0,%1,%2,%3}, [%4];"
                 : "=r"(v.x), "=r"(v.y), "=r"(v.z), "=r"(v.w) : "l"(p));
    return v;
}
__device__ __forceinline__ unsigned ld_acq(const unsigned* p) {
    unsigned v;
    asm volatile("ld.acquire.gpu.global.u32 %0, [%1];" : "=r"(v) : "l"(p));
    return v;
}
__device__ __forceinline__ void st_release_u32(unsigned* p, unsigned v) {
    asm volatile("st.release.gpu.global.u32 [%0], %1;" :: "l"(p), "r"(v) : "memory");
}
__device__ __forceinline__ void prefetch_l2(const void* p) {
    asm volatile("prefetch.global.L2 [%0];" :: "l"(p));
}

__device__ __forceinline__ void mma16816(float* acc, const uint4& a, const uint2& b) {
    asm volatile(
        "mma.sync.aligned.m16n8k16.row.col.f32.f16.f16.f32 "
        "{%0,%1,%2,%3}, {%4,%5,%6,%7}, {%8,%9}, {%0,%1,%2,%3};\n"
        : "+f"(acc[0]), "+f"(acc[1]), "+f"(acc[2]), "+f"(acc[3])
        : "r"(a.x), "r"(a.y), "r"(a.z), "r"(a.w), "r"(b.x), "r"(b.y));
}

__global__ void __launch_bounds__(NTHR, 1)
k_lstm_layer(int layer,
             const float* __restrict__ bih, const float* __restrict__ bhh,
             float* __restrict__ out,          // fp32 [T,B,H] (layer1) or null
             float* __restrict__ nh, float* __restrict__ nc) {
    __shared__ float s_red[2][8 * RED_STRIDE];   // 34816 B, parity buffered

    const uint32_t* xfrag = layer ? g_xfrag1 : g_xfrag0;

    const int tid = threadIdx.x, warp = tid >> 5, lane = tid & 31;
    const int cblk = blockIdx.x;
    const int g = lane >> 2, tq = lane & 3;

    // ---- weights -> registers: warp covers x-kk [warp*8,+8) and h-kk 64+[warp*8,+8)
    uint2 bxr[8][4], bhr[8][4];
    {
        const uint32_t* wf = g_wfrag[layer] + (size_t)cblk * 32768;
        #pragma unroll
        for (int j = 0; j < 8; j++) {
            #pragma unroll
            for (int nt = 0; nt < 4; nt++) {
                int kkx = warp * 8 + j;
                int kkh = 64 + warp * 8 + j;
                bxr[j][nt] = *(const uint2*)&wf[((kkx * 4 + nt) * 32 + lane) * 2];
                bhr[j][nt] = *(const uint2*)&wf[((kkh * 4 + nt) * 32 + lane) * 2];
            }
        }
    }

    // ---- cell-thread state (tid<128): b = tid&15, unit u = cblk*8 + (tid>>4)
    float cc = 0.f, bs0 = 0.f, bs1 = 0.f, bs2 = 0.f, bs3 = 0.f;
    int b = 0, u = 0, h_a32 = 0;
    if (tid < 128) {
        b = tid & 15;
        int lu = tid >> 4;
        u = cblk * 8 + lu;
        bs0 = bih[u]        + bhh[u];
        bs1 = bih[H_ + u]   + bhh[H_ + u];
        bs2 = bih[2*H_ + u] + bhh[2*H_ + u];
        bs3 = bih[3*H_ + u] + bhh[3*H_ + u];
        int ue = u & ~1;
        int kl = ue & 15;
        int tq_ = (kl >> 1) & 3;
        int rr  = (b >> 3) + ((kl >> 3) << 1);
        int ln_ = ((b & 7) << 2) | tq_;
        h_a32 = ((ue >> 4) * 32 + ln_) * 4 + rr;
    }
    // producer-warp flags this warp must poll: pairs [64*warp, 64*warp+64)
    const int fbase = warp * 64;
    __syncthreads();

    #pragma unroll 1
    for (int t = 0; t < T_; ++t) {
        // ---- issue x A-frag LDGs (land during poll) + L2 prefetch x[t+1] ----
        uint4 ax[8];
        {
            const uint4* xa = (const uint4*)(xfrag + (size_t)t * XFRAG_T);
            #pragma unroll
            for (int j = 0; j < 8; j++)
                ax[j] = ldcg4(xa + ((warp * 8 + j) * 32 + lane));
        }
        if (t + 1 < T_) {
            const uint4* xn = (const uint4*)(xfrag + (size_t)(t + 1) * XFRAG_T);
            #pragma unroll
            for (int j = 0; j < 8; j++)
                prefetch_l2(xn + ((warp * 8 + j) * 32 + lane));
        }

        // ---- targeted poll: my 64 producer warps done with step t-1 ----
        if (t) {
            const unsigned tgt = (unsigned)t;
            for (;;) {
                unsigned v0 = ld_acq(&g_wflags[fbase + lane]);
                unsigned v1 = ld_acq(&g_wflags[fbase + 32 + lane]);
                if (__all_sync(0xffffffffu, (v0 >= tgt) & (v1 >= tgt))) break;
                __nanosleep(20);
            }
        }

        // ---- issue h A-frag LDGs (land during x-GEMM) ----
        uint4 ah[8];
        {
            const uint4* ha = (const uint4*)(g_hfrag + (size_t)(t & 1) * HFRAG_SZ);
            #pragma unroll
            for (int j = 0; j < 8; j++)
                ah[j] = ldcg4(ha + ((warp * 8 + j) * 32 + lane));
        }

        float acc[4][4];
        #pragma unroll
        for (int nt = 0; nt < 4; nt++)
            #pragma unroll
            for (int j = 0; j < 4; j++) acc[nt][j] = 0.f;

        #pragma unroll
        for (int j = 0; j < 8; j++) {
            #pragma unroll
            for (int nt = 0; nt < 4; nt++) mma16816(acc[nt], ax[j], bxr[j][nt]);
        }
        #pragma unroll
        for (int j = 0; j < 8; j++) {
            #pragma unroll
            for (int nt = 0; nt < 4; nt++) mma16816(acc[nt], ah[j], bhr[j][nt]);
        }

        // ---- partials -> s_red[t&1][warp][row(b)][col] ----
        {
            float* rp = s_red[t & 1] + warp * RED_STRIDE;
            #pragma unroll
            for (int nt = 0; nt < 4; nt++) {
                int col = nt * 8 + tq * 2;
                *(float2*)&rp[g * 34 + col]       = make_float2(acc[nt][0], acc[nt][1]);
                *(float2*)&rp[(g + 8) * 34 + col] = make_float2(acc[nt][2], acc[nt][3]);
            }
        }
        __syncthreads();     // the ONLY per-step CTA sync

        // ---- cell update (warps 0-3); other warps run ahead (skew <= 1 step)
        if (tid < 128) {
            int lu = tid >> 4;
            float gi = bs0, gf = bs1, gg = bs2, go = bs3;
            const float* rb = s_red[t & 1] + b * 34;
            #pragma unroll
            for (int w = 0; w < 8; w++) {
                const float* rp = rb + w * RED_STRIDE;
                gi += rp[lu];
                gf += rp[8 + lu];
                gg += rp[16 + lu];
                go += rp[24 + lu];
            }
            float fi = sigmoid_ap(gi);
            float ff = sigmoid_ap(gf);
            float fg = tanh_ap(gg);
            float fo = sigmoid_ap(go);
            cc = ff * cc + fi * fg;
            float hv = fo * tanh_ap(cc);

            unsigned us = (unsigned)__half_as_ushort(__float2half_rn(hv));
            unsigned other = __shfl_xor_sync(0xffffffffu, us, 16);
            if (lane < 16) {                       // pack (even u | odd u)
                uint32_t packed = us | (other << 16);
                g_hfrag[(size_t)((t + 1) & 1) * HFRAG_SZ + h_a32] = packed;
                if (layer == 0)
                    g_xfrag1[(size_t)t * XFRAG_T + h_a32] = packed;
            }
            if (layer == 1)
                out[((size_t)t * B_ + b) * H_ + u] = hv;
            if (t == T_ - 1 && nh) {
                nh[b * H_ + u] = hv;
                nc[b * H_ + u] = cc;
            }
            // publish this warp's unit pair: flag id = 4*cblk + warp
            __syncwarp();
            if (lane == 0)
                st_release_u32(&g_wflags[cblk * 4 + warp], (unsigned)(t + 1));
        }
    }
}

// ---------------------------------------------------------------------------
extern "C" void kernel_launch(void* const* d_in, const int* in_sizes, int n_in,
                              void* d_out, int out_size) {
    const float* x    = (const float*)d_in[0];
    const float* Wih0 = (const float*)d_in[1];
    const float* bih0 = (const float*)d_in[2];
    const float* Whh0 = (const float*)d_in[3];
    const float* bhh0 = (const float*)d_in[4];
    const float* Wih1 = (const float*)d_in[5];
    const float* bih1 = (const float*)d_in[6];
    const float* Whh1 = (const float*)d_in[7];
    const float* bhh1 = (const float*)d_in[8];
    float* out = (float*)d_out;

    float* nh = nullptr;
    float* nc = nullptr;
    const size_t out1_sz = (size_t)T_ * B_ * H_;
    if ((size_t)out_size >= out1_sz + 4 * B_ * H_) {
        nh = out + out1_sz;
        nc = nh + 2 * B_ * H_;
    }

    dim3 gw(2048, 2);
    k_conv_w<<<gw, 256>>>(Wih0, Whh0, Wih1, Whh1);
    k_conv_x<<<4096, 256>>>(x);

    k_reset<<<128, 256>>>();
    k_lstm_layer<<<NCTA, NTHR>>>(0, bih0, bhh0, nullptr, nh, nc);
    k_reset<<<128, 256>>>();
    k_lstm_layer<<<NCTA, NTHR>>>(1, bih1, bhh1, out,
                                 nh ? nh + B_ * H_ : nullptr,
                                 nc ? nc + B_ * H_ : nullptr);
}

// round 9
// speedup vs baseline: 1.2163x; 1.2163x over previous
#include <cuda_runtime.h>
#include <cuda_fp16.h>
#include <cstdint>
#include <cstddef>

// 2-layer LSTM, T=1024, B=16, I=H=1024.
// Persistent per-layer kernels; register weights; cp.async x staging with
// parity double-buffering (one syncthreads/step); split x-GEMM around the
// poll; early flag release via named barrier among cell warps.
#define T_   1024
#define B_   16
#define H_   1024
#define NCTA 128
#define NTHR 256
#define WFRAG_L (NCTA*128*4*32*2)     // u32 per layer = 4,194,304
#define XFRAG_T 8192                  // u32 per timestep A-frag (32 KB)
#define HFRAG_SZ XFRAG_T
#define RED_STRIDE 544                // 16 rows * 34 floats per warp
// smem: s_x[2][8192] u32 (64 KB) + s_red[2][8*544] f32 (34816 B)
#define SMEM_BYTES (2*8192*4 + 2*8*RED_STRIDE*4)   // 100352 B

__device__ __align__(16) uint32_t g_wfrag[2][WFRAG_L];
__device__ __align__(16) uint32_t g_xfrag0[(size_t)T_*XFRAG_T];
__device__ __align__(16) uint32_t g_xfrag1[(size_t)T_*XFRAG_T];
__device__ __align__(16) uint32_t g_hfrag[2*HFRAG_SZ];
__device__ __align__(16) unsigned g_flags[NCTA];

// ---------------------------------------------------------------------------
__global__ void k_reset() {
    int i = blockIdx.x * blockDim.x + threadIdx.x;
    if (i < 2*HFRAG_SZ) g_hfrag[i] = 0u;
    if (i < NCTA) g_flags[i] = 0u;
}

// B-frag layout for [Wih;Whh]: idx = (((c*128+kk)*4+nt)*32+lane)*2+p
// lane=4g+tq ; W row = nt*H + c*8 + g ; k = (kk&63)*16 + 2tq + 8p + {0,1}
// kk<64 -> Wih, kk>=64 -> Whh
__global__ void k_conv_w(const float* __restrict__ Wih0, const float* __restrict__ Whh0,
                         const float* __restrict__ Wih1, const float* __restrict__ Whh1) {
    int layer = blockIdx.y;
    const float* Wih = layer ? Wih1 : Wih0;
    const float* Whh = layer ? Whh1 : Whh0;
    int stride = gridDim.x * blockDim.x;
    for (int idx = blockIdx.x * blockDim.x + threadIdx.x; idx < WFRAG_L; idx += stride) {
        int p    = idx & 1;
        int lane = (idx >> 1) & 31;
        int nt   = (idx >> 6) & 3;
        int kk   = (idx >> 8) & 127;
        int c    = idx >> 15;
        int g = lane >> 2, tq = lane & 3;
        int row = nt * H_ + c * 8 + g;
        int kl  = (kk & 63) * 16 + tq * 2 + p * 8;
        const float2 v = *reinterpret_cast<const float2*>(
            (kk < 64 ? Wih : Whh) + (size_t)row * H_ + kl);
        __half2 hv = __floats2half2_rn(v.x, v.y);
        g_wfrag[layer][idx] = *reinterpret_cast<uint32_t*>(&hv);
    }
}

// A-frag layout for x: per-t idx = (kk*32+lane)*4 + r ; b = g + 8*(r&1) ;
// k = kk*16 + 2tq + 8*(r>>1) + {0,1}
__global__ void k_conv_x(const float* __restrict__ x) {
    size_t total = (size_t)T_ * XFRAG_T;
    size_t stride = (size_t)gridDim.x * blockDim.x;
    for (size_t idx = (size_t)blockIdx.x * blockDim.x + threadIdx.x; idx < total; idx += stride) {
        int it = (int)(idx >> 13);
        int r8 = (int)(idx & (XFRAG_T - 1));
        int kk   = r8 >> 7;
        int lane = (r8 >> 2) & 31;
        int r    = r8 & 3;
        int g = lane >> 2, tq = lane & 3;
        int b  = g + ((r & 1) << 3);
        int kb = kk * 16 + tq * 2 + ((r >> 1) << 3);
        const float2 v = *reinterpret_cast<const float2*>(
            x + ((size_t)it * B_ + b) * H_ + kb);
        __half2 hv = __floats2half2_rn(v.x, v.y);
        g_xfrag0[idx] = *reinterpret_cast<uint32_t*>(&hv);
    }
}

// ---------------------------------------------------------------------------
__device__ __forceinline__ float tanh_ap(float v) {
    float r;
    asm("tanh.approx.f32 %0, %1;" : "=f"(r) : "f"(v));
    return r;
}
__device__ __forceinline__ float sigmoid_ap(float v) {
    return fmaf(tanh_ap(0.5f * v), 0.5f, 0.5f);
}

__device__ __forceinline__ void cpa16(uint32_t dst, const void* src) {
    asm volatile("cp.async.cg.shared.global [%0], [%1], 16;" :: "r"(dst), "l"(src));
}
#define CP_COMMIT asm volatile("cp.async.commit_group;")
#define CP_WAIT0  asm volatile("cp.async.wait_group 0;")

__device__ __forceinline__ uint4 ldcg4(const uint4* p) {
    uint4 v;
    asm volatile("ld.global.cg.v4.u32 {%0,%1,%2,%3}, [%4];"
                 : "=r"(v.x), "=r"(v.y), "=r"(v.z), "=r"(v.w) : "l"(p));
    return v;
}
__device__ __forceinline__ unsigned ld_acq(const unsigned* p) {
    unsigned v;
    asm volatile("ld.acquire.gpu.global.u32 %0, [%1];" : "=r"(v) : "l"(p));
    return v;
}
__device__ __forceinline__ void st_release_u32(unsigned* p, unsigned v) {
    asm volatile("st.release.gpu.global.u32 [%0], %1;" :: "l"(p), "r"(v) : "memory");
}

__device__ __forceinline__ void mma16816(float* acc, const uint4& a, const uint2& b) {
    asm volatile(
        "mma.sync.aligned.m16n8k16.row.col.f32.f16.f16.f32 "
        "{%0,%1,%2,%3}, {%4,%5,%6,%7}, {%8,%9}, {%0,%1,%2,%3};\n"
        : "+f"(acc[0]), "+f"(acc[1]), "+f"(acc[2]), "+f"(acc[3])
        : "r"(a.x), "r"(a.y), "r"(a.z), "r"(a.w), "r"(b.x), "r"(b.y));
}

__global__ void __launch_bounds__(NTHR, 1)
k_lstm_layer(int layer,
             const float* __restrict__ bih, const float* __restrict__ bhh,
             float* __restrict__ out,          // fp32 [T,B,H] (layer1) or null
             float* __restrict__ nh, float* __restrict__ nc) {
    extern __shared__ uint32_t smem[];
    uint32_t* s_x0  = smem;                    // parity 0 x A-frag
    uint32_t* s_x1  = smem + 8192;             // parity 1 x A-frag
    float*    s_red = (float*)(smem + 16384);  // [2][8*544] floats

    uint32_t sbase;
    asm("{ .reg .u64 t; cvta.to.shared.u64 t, %1; cvt.u32.u64 %0, t; }"
        : "=r"(sbase) : "l"(smem));

    const uint32_t* xfrag = layer ? g_xfrag1 : g_xfrag0;

    const int tid = threadIdx.x, warp = tid >> 5, lane = tid & 31;
    const int cblk = blockIdx.x;
    const int g = lane >> 2, tq = lane & 3;

    // ---- weights -> registers: warp covers x-kk [warp*8,+8) and h-kk 64+[warp*8,+8)
    uint2 bxr[8][4], bhr[8][4];
    {
        const uint32_t* wf = g_wfrag[layer] + (size_t)cblk * 32768;
        #pragma unroll
        for (int j = 0; j < 8; j++) {
            #pragma unroll
            for (int nt = 0; nt < 4; nt++) {
                int kkx = warp * 8 + j;
                int kkh = 64 + warp * 8 + j;
                bxr[j][nt] = *(const uint2*)&wf[((kkx * 4 + nt) * 32 + lane) * 2];
                bhr[j][nt] = *(const uint2*)&wf[((kkh * 4 + nt) * 32 + lane) * 2];
            }
        }
    }

    // ---- prologue: x[0] -> s_x0 via cp.async
    {
        const uint4* xs = (const uint4*)xfrag;
        #pragma unroll
        for (int i = 0; i < 8; i++) cpa16(sbase + (tid + i*NTHR)*16u, xs + tid + i*NTHR);
        CP_COMMIT; CP_WAIT0;
    }

    // ---- cell-thread state (tid<128): b = tid&15, unit u = cblk*8 + (tid>>4)
    float cc = 0.f, bs0 = 0.f, bs1 = 0.f, bs2 = 0.f, bs3 = 0.f;
    int b = 0, u = 0, h_a32 = 0;
    if (tid < 128) {
        b = tid & 15;
        int lu = tid >> 4;
        u = cblk * 8 + lu;
        bs0 = bih[u]        + bhh[u];
        bs1 = bih[H_ + u]   + bhh[H_ + u];
        bs2 = bih[2*H_ + u] + bhh[2*H_ + u];
        bs3 = bih[3*H_ + u] + bhh[3*H_ + u];
        int ue = u & ~1;
        int kl = ue & 15;
        int tq_ = (kl >> 1) & 3;
        int rr  = (b >> 3) + ((kl >> 3) << 1);
        int ln_ = ((b & 7) << 2) | tq_;
        h_a32 = ((ue >> 4) * 32 + ln_) * 4 + rr;
    }
    // this warp polls producer CTAs [16*warp, 16*warp+16)
    const int myflag = warp * 16 + (lane & 15);
    __syncthreads();

    #pragma unroll 1
    for (int t = 0; t < T_; ++t) {
        const uint32_t* s_x  = (t & 1) ? s_x1 : s_x0;
        const uint32_t  A_XN = sbase + (uint32_t)(((t + 1) & 1) ? 8192*4 : 0);
        float* red = s_red + (t & 1) * (8 * RED_STRIDE);

        float acc[4][4];
        #pragma unroll
        for (int nt = 0; nt < 4; nt++)
            #pragma unroll
            for (int j = 0; j < 4; j++) acc[nt][j] = 0.f;

        // ---- x-GEMM part 1 (producer-independent overlap) ----
        #pragma unroll
        for (int j = 0; j < 4; j++) {
            uint4 a = *(const uint4*)&s_x[((warp * 8 + j) * 32 + lane) * 4];
            #pragma unroll
            for (int nt = 0; nt < 4; nt++) mma16816(acc[nt], a, bxr[j][nt]);
        }

        // ---- stage x[t+1] into the other parity buffer (no sync needed) ----
        if (t + 1 < T_) {
            const uint4* xs = (const uint4*)(xfrag + (size_t)(t + 1) * XFRAG_T);
            #pragma unroll
            for (int i = 0; i < 8; i++) cpa16(A_XN + (tid + i*NTHR)*16u, xs + tid + i*NTHR);
        }
        CP_COMMIT;

        // ---- targeted poll: my 16 producer CTAs done with step t-1 ----
        if (t) {
            const unsigned tgt = (unsigned)t;
            for (;;) {
                unsigned v = ld_acq(&g_flags[myflag]);
                if (__all_sync(0xffffffffu, v >= tgt)) break;
                __nanosleep(20);
            }
        }

        // ---- issue h A-frag LDGs; latency hidden by x-GEMM part 2 ----
        uint4 ah[8];
        {
            const uint4* ha = (const uint4*)(g_hfrag + (size_t)(t & 1) * HFRAG_SZ);
            #pragma unroll
            for (int j = 0; j < 8; j++)
                ah[j] = ldcg4(ha + ((warp * 8 + j) * 32 + lane));
        }

        // ---- x-GEMM part 2 ----
        #pragma unroll
        for (int j = 4; j < 8; j++) {
            uint4 a = *(const uint4*)&s_x[((warp * 8 + j) * 32 + lane) * 4];
            #pragma unroll
            for (int nt = 0; nt < 4; nt++) mma16816(acc[nt], a, bxr[j][nt]);
        }

        // ---- h-GEMM ----
        #pragma unroll
        for (int j = 0; j < 8; j++) {
            #pragma unroll
            for (int nt = 0; nt < 4; nt++) mma16816(acc[nt], ah[j], bhr[j][nt]);
        }

        // ---- partials -> red[warp][row(b)][col] ----
        {
            float* rp = red + warp * RED_STRIDE;
            #pragma unroll
            for (int nt = 0; nt < 4; nt++) {
                int col = nt * 8 + tq * 2;
                *(float2*)&rp[g * 34 + col]       = make_float2(acc[nt][0], acc[nt][1]);
                *(float2*)&rp[(g + 8) * 34 + col] = make_float2(acc[nt][2], acc[nt][3]);
            }
        }
        CP_WAIT0;            // x[t+1] staged (cross-thread visibility via sync)
        __syncthreads();     // the ONLY full-CTA sync per step

        // ---- cell update (warps 0-3); warps 4-7 run ahead (skew <= 1) ----
        if (tid < 128) {
            int lu = tid >> 4;
            float gi = bs0, gf = bs1, gg = bs2, go = bs3;
            const float* rb = red + b * 34;
            #pragma unroll
            for (int w = 0; w < 8; w++) {
                const float* rp = rb + w * RED_STRIDE;
                gi += rp[lu];
                gf += rp[8 + lu];
                gg += rp[16 + lu];
                go += rp[24 + lu];
            }
            float fi = sigmoid_ap(gi);
            float ff = sigmoid_ap(gf);
            float fg = tanh_ap(gg);
            float fo = sigmoid_ap(go);
            cc = ff * cc + fi * fg;
            float hv = fo * tanh_ap(cc);

            unsigned us = (unsigned)__half_as_ushort(__float2half_rn(hv));
            unsigned other = __shfl_xor_sync(0xffffffffu, us, 16);
            uint32_t packed = us | (other << 16);
            if (lane < 16)                         // pack (even u | odd u)
                g_hfrag[(size_t)((t + 1) & 1) * HFRAG_SZ + h_a32] = packed;

            // publish early: h stores of all 4 cell warps ordered by named bar,
            // then one release store
            asm volatile("bar.sync 1, 128;" ::: "memory");
            if (tid == 0)
                st_release_u32(&g_flags[cblk], (unsigned)(t + 1));

            // off-critical-path stores
            if (layer == 0 && lane < 16)
                g_xfrag1[(size_t)t * XFRAG_T + h_a32] = packed;
            if (layer == 1)
                out[((size_t)t * B_ + b) * H_ + u] = hv;
            if (t == T_ - 1 && nh) {
                nh[b * H_ + u] = hv;
                nc[b * H_ + u] = cc;
            }
        }
    }
}

// ---------------------------------------------------------------------------
extern "C" void kernel_launch(void* const* d_in, const int* in_sizes, int n_in,
                              void* d_out, int out_size) {
    const float* x    = (const float*)d_in[0];
    const float* Wih0 = (const float*)d_in[1];
    const float* bih0 = (const float*)d_in[2];
    const float* Whh0 = (const float*)d_in[3];
    const float* bhh0 = (const float*)d_in[4];
    const float* Wih1 = (const float*)d_in[5];
    const float* bih1 = (const float*)d_in[6];
    const float* Whh1 = (const float*)d_in[7];
    const float* bhh1 = (const float*)d_in[8];
    float* out = (float*)d_out;

    float* nh = nullptr;
    float* nc = nullptr;
    const size_t out1_sz = (size_t)T_ * B_ * H_;
    if ((size_t)out_size >= out1_sz + 4 * B_ * H_) {
        nh = out + out1_sz;
        nc = nh + 2 * B_ * H_;
    }

    static bool attr_done = false;
    if (!attr_done) {
        cudaFuncSetAttribute(k_lstm_layer,
                             cudaFuncAttributeMaxDynamicSharedMemorySize, SMEM_BYTES);
        attr_done = true;
    }

    dim3 gw(2048, 2);
    k_conv_w<<<gw, 256>>>(Wih0, Whh0, Wih1, Whh1);
    k_conv_x<<<4096, 256>>>(x);

    k_reset<<<128, 256>>>();
    k_lstm_layer<<<NCTA, NTHR, SMEM_BYTES>>>(0, bih0, bhh0, nullptr, nh, nc);
    k_reset<<<128, 256>>>();
    k_lstm_layer<<<NCTA, NTHR, SMEM_BYTES>>>(1, bih1, bhh1, out,
                                             nh ? nh + B_ * H_ : nullptr,
                                             nc ? nc + B_ * H_ : nullptr);
}

// round 10
// speedup vs baseline: 1.8429x; 1.5152x over previous
#include <cuda_runtime.h>
#include <cuda_fp16.h>
#include <cstdint>
#include <cstddef>

// 2-layer LSTM, T=1024, B=16, I=H=1024.
// Persistent per-layer kernels; register weights; parity-buffered cp.async x
// staging; x-GEMM split around a targeted producer poll; h direct from L2;
// early flag release (named bar among cell warps); NO warp run-ahead.
#define T_   1024
#define B_   16
#define H_   1024
#define NCTA 128
#define NTHR 256
#define WFRAG_L (NCTA*128*4*32*2)     // u32 per layer = 4,194,304
#define XFRAG_T 8192                  // u32 per timestep A-frag (32 KB)
#define HFRAG_SZ XFRAG_T
#define RED_STRIDE 544                // 16 rows * 34 floats per warp
// smem: s_x[2][8192] u32 (64 KB) + s_red[8*544] f32 (17408 B)
#define SMEM_BYTES (2*8192*4 + 8*RED_STRIDE*4)   // 82944 B

__device__ __align__(16) uint32_t g_wfrag[2][WFRAG_L];
__device__ __align__(16) uint32_t g_xfrag0[(size_t)T_*XFRAG_T];
__device__ __align__(16) uint32_t g_xfrag1[(size_t)T_*XFRAG_T];
__device__ __align__(16) uint32_t g_hfrag[2*HFRAG_SZ];
__device__ __align__(16) unsigned g_flags[NCTA];

// ---------------------------------------------------------------------------
__global__ void k_reset() {
    int i = blockIdx.x * blockDim.x + threadIdx.x;
    if (i < 2*HFRAG_SZ) g_hfrag[i] = 0u;
    if (i < NCTA) g_flags[i] = 0u;
}

// B-frag layout for [Wih;Whh]: idx = (((c*128+kk)*4+nt)*32+lane)*2+p
// lane=4g+tq ; W row = nt*H + c*8 + g ; k = (kk&63)*16 + 2tq + 8p + {0,1}
// kk<64 -> Wih, kk>=64 -> Whh
__global__ void k_conv_w(const float* __restrict__ Wih0, const float* __restrict__ Whh0,
                         const float* __restrict__ Wih1, const float* __restrict__ Whh1) {
    int layer = blockIdx.y;
    const float* Wih = layer ? Wih1 : Wih0;
    const float* Whh = layer ? Whh1 : Whh0;
    int stride = gridDim.x * blockDim.x;
    for (int idx = blockIdx.x * blockDim.x + threadIdx.x; idx < WFRAG_L; idx += stride) {
        int p    = idx & 1;
        int lane = (idx >> 1) & 31;
        int nt   = (idx >> 6) & 3;
        int kk   = (idx >> 8) & 127;
        int c    = idx >> 15;
        int g = lane >> 2, tq = lane & 3;
        int row = nt * H_ + c * 8 + g;
        int kl  = (kk & 63) * 16 + tq * 2 + p * 8;
        const float2 v = *reinterpret_cast<const float2*>(
            (kk < 64 ? Wih : Whh) + (size_t)row * H_ + kl);
        __half2 hv = __floats2half2_rn(v.x, v.y);
        g_wfrag[layer][idx] = *reinterpret_cast<uint32_t*>(&hv);
    }
}

// A-frag layout for x: per-t idx = (kk*32+lane)*4 + r ; b = g + 8*(r&1) ;
// k = kk*16 + 2tq + 8*(r>>1) + {0,1}
__global__ void k_conv_x(const float* __restrict__ x) {
    size_t total = (size_t)T_ * XFRAG_T;
    size_t stride = (size_t)gridDim.x * blockDim.x;
    for (size_t idx = (size_t)blockIdx.x * blockDim.x + threadIdx.x; idx < total; idx += stride) {
        int it = (int)(idx >> 13);
        int r8 = (int)(idx & (XFRAG_T - 1));
        int kk   = r8 >> 7;
        int lane = (r8 >> 2) & 31;
        int r    = r8 & 3;
        int g = lane >> 2, tq = lane & 3;
        int b  = g + ((r & 1) << 3);
        int kb = kk * 16 + tq * 2 + ((r >> 1) << 3);
        const float2 v = *reinterpret_cast<const float2*>(
            x + ((size_t)it * B_ + b) * H_ + kb);
        __half2 hv = __floats2half2_rn(v.x, v.y);
        g_xfrag0[idx] = *reinterpret_cast<uint32_t*>(&hv);
    }
}

// ---------------------------------------------------------------------------
__device__ __forceinline__ float tanh_ap(float v) {
    float r;
    asm("tanh.approx.f32 %0, %1;" : "=f"(r) : "f"(v));
    return r;
}
__device__ __forceinline__ float sigmoid_ap(float v) {
    return fmaf(tanh_ap(0.5f * v), 0.5f, 0.5f);
}

__device__ __forceinline__ void cpa16(uint32_t dst, const void* src) {
    asm volatile("cp.async.cg.shared.global [%0], [%1], 16;" :: "r"(dst), "l"(src));
}
#define CP_COMMIT asm volatile("cp.async.commit_group;")
#define CP_WAIT0  asm volatile("cp.async.wait_group 0;")

__device__ __forceinline__ uint4 ldcg4(const uint4* p) {
    uint4 v;
    asm volatile("ld.global.cg.v4.u32 {%0,%1,%2,%3}, [%4];"
                 : "=r"(v.x), "=r"(v.y), "=r"(v.z), "=r"(v.w) : "l"(p));
    return v;
}
__device__ __forceinline__ unsigned ld_acq(const unsigned* p) {
    unsigned v;
    asm volatile("ld.acquire.gpu.global.u32 %0, [%1];" : "=r"(v) : "l"(p));
    return v;
}
__device__ __forceinline__ void st_release_u32(unsigned* p, unsigned v) {
    asm volatile("st.release.gpu.global.u32 [%0], %1;" :: "l"(p), "r"(v) : "memory");
}

__device__ __forceinline__ void mma16816(float* acc, const uint4& a, const uint2& b) {
    asm volatile(
        "mma.sync.aligned.m16n8k16.row.col.f32.f16.f16.f32 "
        "{%0,%1,%2,%3}, {%4,%5,%6,%7}, {%8,%9}, {%0,%1,%2,%3};\n"
        : "+f"(acc[0]), "+f"(acc[1]), "+f"(acc[2]), "+f"(acc[3])
        : "r"(a.x), "r"(a.y), "r"(a.z), "r"(a.w), "r"(b.x), "r"(b.y));
}

__global__ void __launch_bounds__(NTHR, 1)
k_lstm_layer(int layer,
             const float* __restrict__ bih, const float* __restrict__ bhh,
             float* __restrict__ out,          // fp32 [T,B,H] (layer1) or null
             float* __restrict__ nh, float* __restrict__ nc) {
    extern __shared__ uint32_t smem[];
    uint32_t* s_x0  = smem;                    // parity 0 x A-frag
    uint32_t* s_x1  = smem + 8192;             // parity 1 x A-frag
    float*    s_red = (float*)(smem + 16384);  // 8*544 floats

    uint32_t sbase;
    asm("{ .reg .u64 t; cvta.to.shared.u64 t, %1; cvt.u32.u64 %0, t; }"
        : "=r"(sbase) : "l"(smem));

    const uint32_t* xfrag = layer ? g_xfrag1 : g_xfrag0;

    const int tid = threadIdx.x, warp = tid >> 5, lane = tid & 31;
    const int cblk = blockIdx.x;
    const int g = lane >> 2, tq = lane & 3;

    // ---- weights -> registers: warp covers x-kk [warp*8,+8) and h-kk 64+[warp*8,+8)
    uint2 bxr[8][4], bhr[8][4];
    {
        const uint32_t* wf = g_wfrag[layer] + (size_t)cblk * 32768;
        #pragma unroll
        for (int j = 0; j < 8; j++) {
            #pragma unroll
            for (int nt = 0; nt < 4; nt++) {
                int kkx = warp * 8 + j;
                int kkh = 64 + warp * 8 + j;
                bxr[j][nt] = *(const uint2*)&wf[((kkx * 4 + nt) * 32 + lane) * 2];
                bhr[j][nt] = *(const uint2*)&wf[((kkh * 4 + nt) * 32 + lane) * 2];
            }
        }
    }

    // ---- prologue: x[0] -> s_x0 via cp.async
    {
        const uint4* xs = (const uint4*)xfrag;
        #pragma unroll
        for (int i = 0; i < 8; i++) cpa16(sbase + (tid + i*NTHR)*16u, xs + tid + i*NTHR);
        CP_COMMIT; CP_WAIT0;
    }

    // ---- cell-thread state (tid<128): b = tid&15, unit u = cblk*8 + (tid>>4)
    float cc = 0.f, bs0 = 0.f, bs1 = 0.f, bs2 = 0.f, bs3 = 0.f;
    int b = 0, u = 0, h_a32 = 0;
    if (tid < 128) {
        b = tid & 15;
        int lu = tid >> 4;
        u = cblk * 8 + lu;
        bs0 = bih[u]        + bhh[u];
        bs1 = bih[H_ + u]   + bhh[H_ + u];
        bs2 = bih[2*H_ + u] + bhh[2*H_ + u];
        bs3 = bih[3*H_ + u] + bhh[3*H_ + u];
        int ue = u & ~1;
        int kl = ue & 15;
        int tq_ = (kl >> 1) & 3;
        int rr  = (b >> 3) + ((kl >> 3) << 1);
        int ln_ = ((b & 7) << 2) | tq_;
        h_a32 = ((ue >> 4) * 32 + ln_) * 4 + rr;
    }
    // this warp polls producer CTAs [16*warp, 16*warp+16)
    const int myflag = warp * 16 + (lane & 15);
    __syncthreads();

    #pragma unroll 1
    for (int t = 0; t < T_; ++t) {
        const uint32_t* s_x  = (t & 1) ? s_x1 : s_x0;
        const uint32_t  A_XN = sbase + (uint32_t)(((t + 1) & 1) ? 8192*4 : 0);

        // ---- stage x[t+1] into the other parity buffer (in flight all step) ----
        if (t + 1 < T_) {
            const uint4* xs = (const uint4*)(xfrag + (size_t)(t + 1) * XFRAG_T);
            #pragma unroll
            for (int i = 0; i < 8; i++) cpa16(A_XN + (tid + i*NTHR)*16u, xs + tid + i*NTHR);
        }
        CP_COMMIT;

        float acc[4][4];
        #pragma unroll
        for (int nt = 0; nt < 4; nt++)
            #pragma unroll
            for (int j = 0; j < 4; j++) acc[nt][j] = 0.f;

        // ---- x-GEMM part 1 (producer-independent) ----
        #pragma unroll
        for (int j = 0; j < 4; j++) {
            uint4 a = *(const uint4*)&s_x[((warp * 8 + j) * 32 + lane) * 4];
            #pragma unroll
            for (int nt = 0; nt < 4; nt++) mma16816(acc[nt], a, bxr[j][nt]);
        }

        // ---- targeted poll: my 16 producer CTAs done with step t-1 ----
        if (t) {
            const unsigned tgt = (unsigned)t;
            for (;;) {
                unsigned v = ld_acq(&g_flags[myflag]);
                if (__all_sync(0xffffffffu, v >= tgt)) break;
                __nanosleep(20);
            }
        }

        // ---- issue h A-frag LDGs; latency hidden by x-GEMM part 2 ----
        uint4 ah[8];
        {
            const uint4* ha = (const uint4*)(g_hfrag + (size_t)(t & 1) * HFRAG_SZ);
            #pragma unroll
            for (int j = 0; j < 8; j++)
                ah[j] = ldcg4(ha + ((warp * 8 + j) * 32 + lane));
        }

        // ---- x-GEMM part 2 ----
        #pragma unroll
        for (int j = 4; j < 8; j++) {
            uint4 a = *(const uint4*)&s_x[((warp * 8 + j) * 32 + lane) * 4];
            #pragma unroll
            for (int nt = 0; nt < 4; nt++) mma16816(acc[nt], a, bxr[j][nt]);
        }

        // ---- h-GEMM ----
        #pragma unroll
        for (int j = 0; j < 8; j++) {
            #pragma unroll
            for (int nt = 0; nt < 4; nt++) mma16816(acc[nt], ah[j], bhr[j][nt]);
        }

        // ---- partials -> s_red[warp][row(b)][col] ----
        {
            float* rp = s_red + warp * RED_STRIDE;
            #pragma unroll
            for (int nt = 0; nt < 4; nt++) {
                int col = nt * 8 + tq * 2;
                *(float2*)&rp[g * 34 + col]       = make_float2(acc[nt][0], acc[nt][1]);
                *(float2*)&rp[(g + 8) * 34 + col] = make_float2(acc[nt][2], acc[nt][3]);
            }
        }
        __syncthreads();                       // red visible to cell warps

        // ---- cell update (warps 0-3); warps 4-7 go idle at the bottom sync ----
        if (tid < 128) {
            int lu = tid >> 4;
            float gi = bs0, gf = bs1, gg = bs2, go = bs3;
            const float* rb = s_red + b * 34;
            #pragma unroll
            for (int w = 0; w < 8; w++) {
                const float* rp = rb + w * RED_STRIDE;
                gi += rp[lu];
                gf += rp[8 + lu];
                gg += rp[16 + lu];
                go += rp[24 + lu];
            }
            float fi = sigmoid_ap(gi);
            float ff = sigmoid_ap(gf);
            float fg = tanh_ap(gg);
            float fo = sigmoid_ap(go);
            cc = ff * cc + fi * fg;
            float hv = fo * tanh_ap(cc);

            unsigned us = (unsigned)__half_as_ushort(__float2half_rn(hv));
            unsigned other = __shfl_xor_sync(0xffffffffu, us, 16);
            uint32_t packed = us | (other << 16);
            if (lane < 16)                     // pack (even u | odd u)
                g_hfrag[(size_t)((t + 1) & 1) * HFRAG_SZ + h_a32] = packed;

            // early publish: h stores of all 4 cell warps HB-ordered by the
            // named barrier, then one release store
            asm volatile("bar.sync 1, 128;" ::: "memory");
            if (tid == 0)
                st_release_u32(&g_flags[cblk], (unsigned)(t + 1));

            // off-critical-path stores
            if (layer == 0 && lane < 16)
                g_xfrag1[(size_t)t * XFRAG_T + h_a32] = packed;
            if (layer == 1)
                out[((size_t)t * B_ + b) * H_ + u] = hv;
            if (t == T_ - 1 && nh) {
                nh[b * H_ + u] = hv;
                nc[b * H_ + u] = cc;
            }
        }
        CP_WAIT0;                              // own x[t+1] group done
        __syncthreads();                       // no run-ahead past this point
    }
}

// ---------------------------------------------------------------------------
extern "C" void kernel_launch(void* const* d_in, const int* in_sizes, int n_in,
                              void* d_out, int out_size) {
    const float* x    = (const float*)d_in[0];
    const float* Wih0 = (const float*)d_in[1];
    const float* bih0 = (const float*)d_in[2];
    const float* Whh0 = (const float*)d_in[3];
    const float* bhh0 = (const float*)d_in[4];
    const float* Wih1 = (const float*)d_in[5];
    const float* bih1 = (const float*)d_in[6];
    const float* Whh1 = (const float*)d_in[7];
    const float* bhh1 = (const float*)d_in[8];
    float* out = (float*)d_out;

    float* nh = nullptr;
    float* nc = nullptr;
    const size_t out1_sz = (size_t)T_ * B_ * H_;
    if ((size_t)out_size >= out1_sz + 4 * B_ * H_) {
        nh = out + out1_sz;
        nc = nh + 2 * B_ * H_;
    }

    static bool attr_done = false;
    if (!attr_done) {
        cudaFuncSetAttribute(k_lstm_layer,
                             cudaFuncAttributeMaxDynamicSharedMemorySize, SMEM_BYTES);
        attr_done = true;
    }

    dim3 gw(2048, 2);
    k_conv_w<<<gw, 256>>>(Wih0, Whh0, Wih1, Whh1);
    k_conv_x<<<4096, 256>>>(x);

    k_reset<<<128, 256>>>();
    k_lstm_layer<<<NCTA, NTHR, SMEM_BYTES>>>(0, bih0, bhh0, nullptr, nh, nc);
    k_reset<<<128, 256>>>();
    k_lstm_layer<<<NCTA, NTHR, SMEM_BYTES>>>(1, bih1, bhh1, out,
                                             nh ? nh + B_ * H_ : nullptr,
                                             nc ? nc + B_ * H_ : nullptr);
}